// round 12
// baseline (speedup 1.0000x reference)
#include <cuda_runtime.h>
#include <cuda_fp16.h>
#include <cstdint>

#define HDIM 1024
#define BDIM 64
#define TM   128
#define NT   256

// ---- dynamic smem byte offsets ----
#define O_SUB 0              // up_b, 4KB fp32
#define O_C1  4096           // 256B
#define O_C2  4352
#define O_MU  4608           // 512B fp32 (128 rows)
#define O_RS  5120
#define O_XA0 6144           // 16KB fp16 tile image [128r][64k]
#define O_XA1 22528
#define O_W0  38912          // 8KB fp16 tile image [64k][64n]
#define O_W1  47104
#define SMEM_BYTES 55296
#define O_H   O_XA0          // h image aliases XA0 after phase A
#define O_S   O_XA0          // phase-B fp32 staging tile (32KB = XA0+XA1)

__device__ __half g_w2h[16 * 4096];   // swizzled [kc][k][unit] images, B=[k][d]
__device__ __half g_uph[16 * 4096];   // swizzled [nc][k][unit] images, B=[d][n]
__device__ float  g_c1[BDIM];
__device__ float  g_c2[BDIM];

// ---------------- helpers ----------------
__device__ __forceinline__ uint32_t smem_u32(const void* p) {
    uint32_t a;
    asm("{ .reg .u64 t; cvta.to.shared.u64 t, %1; cvt.u32.u64 %0, t; }"
        : "=r"(a) : "l"(p));
    return a;
}
__device__ __forceinline__ uint32_t pk2(float a, float b) {
    __half2 h = __floats2half2_rn(a, b);
    return *reinterpret_cast<uint32_t*>(&h);
}
__device__ __forceinline__ void cpa16(uint32_t saddr, const void* g) {
    asm volatile("cp.async.cg.shared.global [%0], [%1], 16;"
                 :: "r"(saddr), "l"(g) : "memory");
}
#define CPA_COMMIT() asm volatile("cp.async.commit_group;" ::: "memory")
#define CPA_WAIT0()  asm volatile("cp.async.wait_group 0;" ::: "memory")

__device__ __forceinline__ void ldm4(uint32_t* r, uint32_t addr) {
    asm volatile("ldmatrix.sync.aligned.m8n8.x4.shared.b16 {%0,%1,%2,%3}, [%4];"
                 : "=r"(r[0]), "=r"(r[1]), "=r"(r[2]), "=r"(r[3]) : "r"(addr));
}
__device__ __forceinline__ void ldm4t(uint32_t* r, uint32_t addr) {
    asm volatile("ldmatrix.sync.aligned.m8n8.x4.trans.shared.b16 {%0,%1,%2,%3}, [%4];"
                 : "=r"(r[0]), "=r"(r[1]), "=r"(r[2]), "=r"(r[3]) : "r"(addr));
}
__device__ __forceinline__ void mma16(float* c, const uint32_t* a,
                                      uint32_t b0, uint32_t b1) {
    asm volatile(
        "mma.sync.aligned.m16n8k16.row.col.f32.f16.f16.f32 "
        "{%0,%1,%2,%3}, {%4,%5,%6,%7}, {%8,%9}, {%0,%1,%2,%3};"
        : "+f"(c[0]), "+f"(c[1]), "+f"(c[2]), "+f"(c[3])
        : "r"(a[0]), "r"(a[1]), "r"(a[2]), "r"(a[3]), "r"(b0), "r"(b1));
}
__device__ __forceinline__ float gelu(float v) {
    return 0.5f * v * (1.0f + erff(v * 0.70710678118654752f));
}

// ---------------- merged prep: images + c1/c2, coalesced ----------------
__global__ void prep_all(const float* __restrict__ down_w,
                         const float* __restrict__ norm_w,
                         const float* __restrict__ norm_b,
                         const float* __restrict__ down_b,
                         const float* __restrict__ up_w) {
    __shared__ float r1[8], r2[8];
    const int t = threadIdx.x, d = blockIdx.x;
    const int log_u = d >> 3, di = d & 7;

    float4 dw = *(const float4*)(down_w + d * HDIM + t * 4);
    float4 nw = *(const float4*)(norm_w + t * 4);
    float4 nb = *(const float4*)(norm_b + t * 4);
    float s1 = 0.f, s2 = 0.f;
    {
        float dwa[4] = {dw.x, dw.y, dw.z, dw.w};
        float nwa[4] = {nw.x, nw.y, nw.z, nw.w};
        float nba[4] = {nb.x, nb.y, nb.z, nb.w};
        #pragma unroll
        for (int j = 0; j < 4; j++) {
            int h = t * 4 + j;
            int k = h & 63, cc = h >> 6;
            __half w2 = __float2half_rn(dwa[j] * nwa[j]);
            g_w2h[cc * 4096 + k * 64 + (log_u ^ (k & 7)) * 8 + di] = w2;
            s1 += __half2float(w2);
            s2 += dwa[j] * nba[j];
        }
    }
    {
        int flat = d * 1024 + t * 4;           // = n*64 + k
        int n = flat >> 6, k0 = flat & 63;
        float4 uv = *(const float4*)(up_w + flat);
        float uva[4] = {uv.x, uv.y, uv.z, uv.w};
        int cc = n >> 6, lu = (n >> 3) & 7, i = n & 7;
        #pragma unroll
        for (int j = 0; j < 4; j++) {
            int k = k0 + j;
            g_uph[cc * 4096 + k * 64 + (lu ^ (k & 7)) * 8 + i] =
                __float2half_rn(uva[j]);
        }
    }
    #pragma unroll
    for (int o = 16; o; o >>= 1) {
        s1 += __shfl_xor_sync(0xffffffffu, s1, o);
        s2 += __shfl_xor_sync(0xffffffffu, s2, o);
    }
    if ((t & 31) == 0) { r1[t >> 5] = s1; r2[t >> 5] = s2; }
    __syncthreads();
    if (t == 0) {
        float a1 = 0.f, a2 = 0.f;
        #pragma unroll
        for (int j = 0; j < 8; j++) { a1 += r1[j]; a2 += r2[j]; }
        g_c1[d] = a1;
        g_c2[d] = a2 + down_b[d];
    }
}

// ---------------- fused main kernel ----------------
__global__ void __launch_bounds__(NT, 2)
adapter_main(const float* __restrict__ x,
             const float* __restrict__ up_b,
             float* __restrict__ out) {
    extern __shared__ char smc[];
    const uint32_t sb = smem_u32(smc);
    float* SUB = (float*)(smc + O_SUB);
    float* C1  = (float*)(smc + O_C1);
    float* C2  = (float*)(smc + O_C2);
    float* MU  = (float*)(smc + O_MU);
    float* RS  = (float*)(smc + O_RS);

    const int tid  = threadIdx.x;
    const int lane = tid & 31, w = tid >> 5;
    const int g    = lane >> 2, t4 = lane & 3;
    const int w_m  = w >> 1,   w_n = w & 1;
    const size_t rbase = (size_t)blockIdx.x * TM;

    // phase-A loader role: 4 lanes per row, rows rq and rq+64
    const int rq = tid >> 2, q = tid & 3;
    const int qh = q >> 1, ql = q & 1;
    // x-image STS offsets (row rq; row rq+64 = +8192)
    int stsA[4];
    #pragma unroll
    for (int j = 0; j < 4; j++) {
        int u = j * 2 + qh;
        stsA[j] = rq * 128 + (((u ^ (rq & 7)) & 15) << 4) + ql * 8;
    }
    // ldmatrix address components (image layout unchanged)
    const int laneq = lane & 7;
    const int half8 = (lane >> 3) & 1;
    const int hi16  = lane >> 4;
    int ofsA[2], colA[4], ofsB[2];
    #pragma unroll
    for (int mt = 0; mt < 2; mt++)
        ofsA[mt] = (w_m * 32 + mt * 16 + half8 * 8 + laneq) * 128;
    #pragma unroll
    for (int kt = 0; kt < 4; kt++)
        colA[kt] = ((kt * 2 + hi16) ^ laneq) * 16;
    {
        int kb0 = half8 * 8 + laneq;
        #pragma unroll
        for (int p = 0; p < 2; p++)
            ofsB[p] = kb0 * 128 + ((w_n * 4 + p * 2 + hi16) ^ laneq) * 16;
    }
    // phase-B staging STS offsets [mt][nt] (row rA; rB = +2048)
    int stg[2][4];
    #pragma unroll
    for (int mt = 0; mt < 2; mt++)
        #pragma unroll
        for (int nt = 0; nt < 4; nt++) {
            int u = w_n * 8 + nt * 2 + (t4 >> 1);
            int r = w_m * 32 + mt * 16 + g;
            stg[mt][nt] = r * 256 + (((u ^ (g << 1)) & 15) << 4) + (t4 & 1) * 8;
        }
    // phase-B output pass constants
    const int po_u  = tid & 15;                 // unit within row
    const int po_r0 = tid >> 4;                 // base row (p adds 16)
    const int po_sw = (((po_u ^ ((po_r0 & 7) << 1)) & 15) << 4);

    for (int i = tid; i < HDIM; i += NT) SUB[i] = up_b[i];
    if (tid < BDIM) { C1[tid] = g_c1[tid]; C2[tid] = g_c2[tid]; }

    float s0 = 0.f, q0 = 0.f, s1 = 0.f, q1 = 0.f;

    // ---- prologue: stage chunk 0 (x regs->smem, weights cp.async) ----
    {
        const char* wg = (const char*)g_w2h + tid * 32;
        cpa16(sb + O_W0 + tid * 32, wg);
        cpa16(sb + O_W0 + tid * 32 + 16, wg + 16);
        CPA_COMMIT();

        const float* xr0 = x + (rbase + rq) * HDIM;
        const float* xr1 = xr0 + 64 * HDIM;
        float4 px[8];
        #pragma unroll
        for (int j = 0; j < 4; j++) px[j]     = *(const float4*)(xr0 + q * 4 + j * 16);
        #pragma unroll
        for (int j = 0; j < 4; j++) px[4 + j] = *(const float4*)(xr1 + q * 4 + j * 16);
        #pragma unroll
        for (int j = 0; j < 4; j++) {
            s0 += (px[j].x + px[j].y) + (px[j].z + px[j].w);
            q0 += px[j].x * px[j].x + px[j].y * px[j].y
                + px[j].z * px[j].z + px[j].w * px[j].w;
            s1 += (px[4+j].x + px[4+j].y) + (px[4+j].z + px[4+j].w);
            q1 += px[4+j].x * px[4+j].x + px[4+j].y * px[4+j].y
                + px[4+j].z * px[4+j].z + px[4+j].w * px[4+j].w;
        }
        #pragma unroll
        for (int j = 0; j < 4; j++) {
            *(uint2*)(smc + O_XA0 + stsA[j]) =
                make_uint2(pk2(px[j].x, px[j].y), pk2(px[j].z, px[j].w));
            *(uint2*)(smc + O_XA0 + stsA[j] + 8192) =
                make_uint2(pk2(px[4+j].x, px[4+j].y), pk2(px[4+j].z, px[4+j].w));
        }
        CPA_WAIT0();
    }
    __syncthreads();

    // ---- phase A: down GEMM, K=1024 in 16 chunks of 64 ----
    float acc[2][4][4];
    #pragma unroll
    for (int mt = 0; mt < 2; mt++)
        #pragma unroll
        for (int nt = 0; nt < 4; nt++)
            #pragma unroll
            for (int j = 0; j < 4; j++) acc[mt][nt][j] = 0.f;

    for (int c = 0; c < 16; c++) {
        float4 px[8];
        if (c + 1 < 16) {
            const int wN = (c & 1) ? O_W0 : O_W1;
            const char* wg = (const char*)g_w2h + (c + 1) * 8192 + tid * 32;
            cpa16(sb + wN + tid * 32, wg);
            cpa16(sb + wN + tid * 32 + 16, wg + 16);
            CPA_COMMIT();
            const float* xr0 = x + (rbase + rq) * HDIM + (c + 1) * 64;
            const float* xr1 = xr0 + 64 * HDIM;
            #pragma unroll
            for (int j = 0; j < 4; j++) px[j]     = *(const float4*)(xr0 + q * 4 + j * 16);
            #pragma unroll
            for (int j = 0; j < 4; j++) px[4 + j] = *(const float4*)(xr1 + q * 4 + j * 16);
        }
        const uint32_t xaB = sb + ((c & 1) ? O_XA1 : O_XA0);
        const uint32_t wB  = sb + ((c & 1) ? O_W1  : O_W0);
        #pragma unroll
        for (int kt = 0; kt < 4; kt++) {
            uint32_t a[2][4], b[2][4];
            ldm4 (a[0], xaB + ofsA[0] + colA[kt]);
            ldm4 (a[1], xaB + ofsA[1] + colA[kt]);
            ldm4t(b[0], wB + kt * 2048 + ofsB[0]);
            ldm4t(b[1], wB + kt * 2048 + ofsB[1]);
            #pragma unroll
            for (int mt = 0; mt < 2; mt++) {
                mma16(acc[mt][0], a[mt], b[0][0], b[0][1]);
                mma16(acc[mt][1], a[mt], b[0][2], b[0][3]);
                mma16(acc[mt][2], a[mt], b[1][0], b[1][1]);
                mma16(acc[mt][3], a[mt], b[1][2], b[1][3]);
            }
        }
        if (c + 1 < 16) {
            const int xaN = (c & 1) ? O_XA0 : O_XA1;
            #pragma unroll
            for (int j = 0; j < 4; j++) {
                s0 += (px[j].x + px[j].y) + (px[j].z + px[j].w);
                q0 += px[j].x * px[j].x + px[j].y * px[j].y
                    + px[j].z * px[j].z + px[j].w * px[j].w;
                s1 += (px[4+j].x + px[4+j].y) + (px[4+j].z + px[4+j].w);
                q1 += px[4+j].x * px[4+j].x + px[4+j].y * px[4+j].y
                    + px[4+j].z * px[4+j].z + px[4+j].w * px[4+j].w;
            }
            #pragma unroll
            for (int j = 0; j < 4; j++) {
                *(uint2*)(smc + xaN + stsA[j]) =
                    make_uint2(pk2(px[j].x, px[j].y), pk2(px[j].z, px[j].w));
                *(uint2*)(smc + xaN + stsA[j] + 8192) =
                    make_uint2(pk2(px[4+j].x, px[4+j].y), pk2(px[4+j].z, px[4+j].w));
            }
            CPA_WAIT0();
        }
        __syncthreads();
    }

    // ---- LN stats: reduce over the 4 q-lanes ----
    {
        s0 += __shfl_xor_sync(0xffffffffu, s0, 1);
        s0 += __shfl_xor_sync(0xffffffffu, s0, 2);
        q0 += __shfl_xor_sync(0xffffffffu, q0, 1);
        q0 += __shfl_xor_sync(0xffffffffu, q0, 2);
        s1 += __shfl_xor_sync(0xffffffffu, s1, 1);
        s1 += __shfl_xor_sync(0xffffffffu, s1, 2);
        q1 += __shfl_xor_sync(0xffffffffu, q1, 1);
        q1 += __shfl_xor_sync(0xffffffffu, q1, 2);
        if (q == 0) {
            float mu  = s0 * (1.0f / HDIM);
            float var = fmaxf(q0 * (1.0f / HDIM) - mu * mu, 0.0f);
            MU[rq] = mu;
            RS[rq] = rsqrtf(var + 1e-5f);
            mu  = s1 * (1.0f / HDIM);
            var = fmaxf(q1 * (1.0f / HDIM) - mu * mu, 0.0f);
            MU[rq + 64] = mu;
            RS[rq + 64] = rsqrtf(var + 1e-5f);
        }
    }
    __syncthreads();

    // ---- epilogue A: LN fixup + bias + exact GELU -> fp16 h image ----
    #pragma unroll
    for (int mt = 0; mt < 2; mt++) {
        int rA = w_m * 32 + mt * 16 + g, rB = rA + 8;
        float mu1 = MU[rA], rs1 = RS[rA], mu2 = MU[rB], rs2 = RS[rB];
        #pragma unroll
        for (int nt = 0; nt < 4; nt++) {
            int n = w_n * 32 + nt * 8 + 2 * t4;
            float c1a = C1[n], c1b = C1[n + 1];
            float c2a = C2[n], c2b = C2[n + 1];
            float g0 = gelu(rs1 * (acc[mt][nt][0] - mu1 * c1a) + c2a);
            float g1 = gelu(rs1 * (acc[mt][nt][1] - mu1 * c1b) + c2b);
            float g2 = gelu(rs2 * (acc[mt][nt][2] - mu2 * c1a) + c2a);
            float g3 = gelu(rs2 * (acc[mt][nt][3] - mu2 * c1b) + c2b);
            int u = (w_n * 4 + nt);
            *(uint32_t*)(smc + O_H + rA * 128 + ((u ^ g) * 16) + t4 * 4) = pk2(g0, g1);
            *(uint32_t*)(smc + O_H + rB * 128 + ((u ^ g) * 16) + t4 * 4) = pk2(g2, g3);
        }
    }
    // stage up-w chunk 15 (phase B runs n-chunks in REVERSE for L2 locality)
    {
        const char* ug = (const char*)g_uph + 15 * 8192 + tid * 32;
        cpa16(sb + O_W0 + tid * 32, ug);
        cpa16(sb + O_W0 + tid * 32 + 16, ug + 16);
        CPA_COMMIT();
        CPA_WAIT0();
    }
    __syncthreads();

    // ---- phase B prologue: h fragments from smem image ----
    uint32_t ha[4][2][4];
    #pragma unroll
    for (int kt = 0; kt < 4; kt++)
        #pragma unroll
        for (int mt = 0; mt < 2; mt++)
            ldm4(ha[kt][mt], sb + O_H + ofsA[mt] + colA[kt]);
    __syncthreads();   // staging below overwrites the h image — all ha loads must land

    // ---- phase B: up GEMM (K=64), n-chunks 15 -> 0 (reverse, LRU-friendly) ----
    for (int ci = 0; ci < 16; ci++) {
        const int nc = 15 - ci;
        const int buf = ci & 1;                 // ci=0 -> W0 (preloaded)
        if (ci + 1 < 16) {
            const int wN = buf ? O_W0 : O_W1;
            const char* ug = (const char*)g_uph + (nc - 1) * 8192 + tid * 32;
            cpa16(sb + wN + tid * 32, ug);
            cpa16(sb + wN + tid * 32 + 16, ug + 16);
            CPA_COMMIT();
        }
        const uint32_t uwB = sb + (buf ? O_W1 : O_W0);
        float ub[2][4][4];
        #pragma unroll
        for (int mt = 0; mt < 2; mt++)
            #pragma unroll
            for (int nt = 0; nt < 4; nt++)
                #pragma unroll
                for (int j = 0; j < 4; j++) ub[mt][nt][j] = 0.f;

        #pragma unroll
        for (int kt = 0; kt < 4; kt++) {
            uint32_t b[2][4];
            ldm4t(b[0], uwB + kt * 2048 + ofsB[0]);
            ldm4t(b[1], uwB + kt * 2048 + ofsB[1]);
            #pragma unroll
            for (int mt = 0; mt < 2; mt++) {
                mma16(ub[mt][0], ha[kt][mt], b[0][0], b[0][1]);
                mma16(ub[mt][1], ha[kt][mt], b[0][2], b[0][3]);
                mma16(ub[mt][2], ha[kt][mt], b[1][0], b[1][1]);
                mma16(ub[mt][3], ha[kt][mt], b[1][2], b[1][3]);
            }
        }

        // stage fragments -> fp32 tile (swizzled)
        #pragma unroll
        for (int mt = 0; mt < 2; mt++)
            #pragma unroll
            for (int nt = 0; nt < 4; nt++) {
                *(float2*)(smc + O_S + stg[mt][nt]) =
                    make_float2(ub[mt][nt][0], ub[mt][nt][1]);
                *(float2*)(smc + O_S + stg[mt][nt] + 2048) =
                    make_float2(ub[mt][nt][2], ub[mt][nt][3]);
            }
        __syncthreads();

        // coalesced output pass: residual (last-use load) + bias + streaming store
        {
            float4 bb = *(const float4*)(SUB + nc * 64 + po_u * 4);
            #pragma unroll
            for (int p = 0; p < 8; p++) {
                int r = po_r0 + p * 16;
                float4 v  = *(const float4*)(smc + O_S + r * 256 + po_sw);
                const size_t go = (rbase + r) * HDIM + nc * 64 + po_u * 4;
                float4 xv = __ldlu((const float4*)(x + go));
                float4 o;
                o.x = xv.x + v.x + bb.x;
                o.y = xv.y + v.y + bb.y;
                o.z = xv.z + v.z + bb.z;
                o.w = xv.w + v.w + bb.w;
                __stcs((float4*)(out + go), o);
            }
        }
        if (ci + 1 < 16) CPA_WAIT0();
        __syncthreads();
    }
}

// ---------------- launch ----------------
extern "C" void kernel_launch(void* const* d_in, const int* in_sizes, int n_in,
                              void* d_out, int out_size) {
    const float* x      = (const float*)d_in[0];
    const float* norm_w = (const float*)d_in[1];
    const float* norm_b = (const float*)d_in[2];
    const float* down_w = (const float*)d_in[3];
    const float* down_b = (const float*)d_in[4];
    const float* up_w   = (const float*)d_in[5];
    const float* up_b   = (const float*)d_in[6];
    float* out = (float*)d_out;

    int rows = in_sizes[0] / HDIM;

    cudaFuncSetAttribute(adapter_main,
                         cudaFuncAttributeMaxDynamicSharedMemorySize, SMEM_BYTES);

    prep_all<<<BDIM, 256>>>(down_w, norm_w, norm_b, down_b, up_w);
    adapter_main<<<rows / TM, NT, SMEM_BYTES>>>(x, up_b, out);
}

// round 13
// speedup vs baseline: 1.4055x; 1.4055x over previous
#include <cuda_runtime.h>
#include <cuda_fp16.h>
#include <cstdint>

#define HDIM 1024
#define BDIM 64
#define TM   128
#define NT   256

// ---- dynamic smem byte offsets ----
#define O_SUB 0              // up_b, 4KB fp32
#define O_C1  4096           // 256B
#define O_C2  4352
#define O_MU  4608           // 512B fp32 (128 rows)
#define O_RS  5120
#define O_XA0 6144           // 16KB fp16 tile image [128r][64k]
#define O_XA1 22528
#define O_W0  38912          // 8KB fp16 tile image [64k][64n]
#define O_W1  47104
#define SMEM_BYTES 55296
#define O_H   O_XA0          // h image aliases XA0 after phase A
#define O_S   O_XA0          // phase-B fp32 staging tile (32KB = XA0+XA1)

__device__ __half g_w2h[16 * 4096];   // swizzled [kc][k][unit] images, B=[k][d]
__device__ __half g_uph[16 * 4096];   // swizzled [nc][k][unit] images, B=[d][n]
__device__ float  g_c1[BDIM];
__device__ float  g_c2[BDIM];

// ---------------- helpers ----------------
__device__ __forceinline__ uint32_t smem_u32(const void* p) {
    uint32_t a;
    asm("{ .reg .u64 t; cvta.to.shared.u64 t, %1; cvt.u32.u64 %0, t; }"
        : "=r"(a) : "l"(p));
    return a;
}
__device__ __forceinline__ uint32_t pk2(float a, float b) {
    __half2 h = __floats2half2_rn(a, b);
    return *reinterpret_cast<uint32_t*>(&h);
}
__device__ __forceinline__ void cpa16(uint32_t saddr, const void* g) {
    asm volatile("cp.async.cg.shared.global [%0], [%1], 16;"
                 :: "r"(saddr), "l"(g) : "memory");
}
#define CPA_COMMIT() asm volatile("cp.async.commit_group;" ::: "memory")
#define CPA_WAIT0()  asm volatile("cp.async.wait_group 0;" ::: "memory")

__device__ __forceinline__ void ldm4(uint32_t* r, uint32_t addr) {
    asm volatile("ldmatrix.sync.aligned.m8n8.x4.shared.b16 {%0,%1,%2,%3}, [%4];"
                 : "=r"(r[0]), "=r"(r[1]), "=r"(r[2]), "=r"(r[3]) : "r"(addr));
}
__device__ __forceinline__ void ldm4t(uint32_t* r, uint32_t addr) {
    asm volatile("ldmatrix.sync.aligned.m8n8.x4.trans.shared.b16 {%0,%1,%2,%3}, [%4];"
                 : "=r"(r[0]), "=r"(r[1]), "=r"(r[2]), "=r"(r[3]) : "r"(addr));
}
__device__ __forceinline__ void mma16(float* c, const uint32_t* a,
                                      uint32_t b0, uint32_t b1) {
    asm volatile(
        "mma.sync.aligned.m16n8k16.row.col.f32.f16.f16.f32 "
        "{%0,%1,%2,%3}, {%4,%5,%6,%7}, {%8,%9}, {%0,%1,%2,%3};"
        : "+f"(c[0]), "+f"(c[1]), "+f"(c[2]), "+f"(c[3])
        : "r"(a[0]), "r"(a[1]), "r"(a[2]), "r"(a[3]), "r"(b0), "r"(b1));
}
__device__ __forceinline__ float gelu(float v) {
    return 0.5f * v * (1.0f + erff(v * 0.70710678118654752f));
}

// ---------------- merged prep: images + c1/c2, coalesced ----------------
__global__ void prep_all(const float* __restrict__ down_w,
                         const float* __restrict__ norm_w,
                         const float* __restrict__ norm_b,
                         const float* __restrict__ down_b,
                         const float* __restrict__ up_w) {
    __shared__ float r1[8], r2[8];
    const int t = threadIdx.x, d = blockIdx.x;
    const int log_u = d >> 3, di = d & 7;

    float4 dw = *(const float4*)(down_w + d * HDIM + t * 4);
    float4 nw = *(const float4*)(norm_w + t * 4);
    float4 nb = *(const float4*)(norm_b + t * 4);
    float s1 = 0.f, s2 = 0.f;
    {
        float dwa[4] = {dw.x, dw.y, dw.z, dw.w};
        float nwa[4] = {nw.x, nw.y, nw.z, nw.w};
        float nba[4] = {nb.x, nb.y, nb.z, nb.w};
        #pragma unroll
        for (int j = 0; j < 4; j++) {
            int h = t * 4 + j;
            int k = h & 63, cc = h >> 6;
            __half w2 = __float2half_rn(dwa[j] * nwa[j]);
            g_w2h[cc * 4096 + k * 64 + (log_u ^ (k & 7)) * 8 + di] = w2;
            s1 += __half2float(w2);
            s2 += dwa[j] * nba[j];
        }
    }
    {
        int flat = d * 1024 + t * 4;           // = n*64 + k
        int n = flat >> 6, k0 = flat & 63;
        float4 uv = *(const float4*)(up_w + flat);
        float uva[4] = {uv.x, uv.y, uv.z, uv.w};
        int cc = n >> 6, lu = (n >> 3) & 7, i = n & 7;
        #pragma unroll
        for (int j = 0; j < 4; j++) {
            int k = k0 + j;
            g_uph[cc * 4096 + k * 64 + (lu ^ (k & 7)) * 8 + i] =
                __float2half_rn(uva[j]);
        }
    }
    #pragma unroll
    for (int o = 16; o; o >>= 1) {
        s1 += __shfl_xor_sync(0xffffffffu, s1, o);
        s2 += __shfl_xor_sync(0xffffffffu, s2, o);
    }
    if ((t & 31) == 0) { r1[t >> 5] = s1; r2[t >> 5] = s2; }
    __syncthreads();
    if (t == 0) {
        float a1 = 0.f, a2 = 0.f;
        #pragma unroll
        for (int j = 0; j < 8; j++) { a1 += r1[j]; a2 += r2[j]; }
        g_c1[d] = a1;
        g_c2[d] = a2 + down_b[d];
    }
}

// ---------------- fused main kernel ----------------
__global__ void __launch_bounds__(NT, 2)
adapter_main(const float* __restrict__ x,
             const float* __restrict__ up_b,
             float* __restrict__ out) {
    extern __shared__ char smc[];
    const uint32_t sb = smem_u32(smc);
    float* SUB = (float*)(smc + O_SUB);
    float* C1  = (float*)(smc + O_C1);
    float* C2  = (float*)(smc + O_C2);
    float* MU  = (float*)(smc + O_MU);
    float* RS  = (float*)(smc + O_RS);

    const int tid  = threadIdx.x;
    const int lane = tid & 31, w = tid >> 5;
    const int g    = lane >> 2, t4 = lane & 3;
    const int w_m  = w >> 1,   w_n = w & 1;
    const size_t rbase = (size_t)blockIdx.x * TM;

    // phase-A loader role: 4 lanes per row, rows rq and rq+64
    const int rq = tid >> 2, q = tid & 3;
    const int qh = q >> 1, ql = q & 1;
    // x-image STS offsets (row rq; row rq+64 = +8192)
    int stsA[4];
    #pragma unroll
    for (int j = 0; j < 4; j++) {
        int u = j * 2 + qh;
        stsA[j] = rq * 128 + (((u ^ (rq & 7)) & 15) << 4) + ql * 8;
    }
    // ldmatrix address components (image layout unchanged)
    const int laneq = lane & 7;
    const int half8 = (lane >> 3) & 1;
    const int hi16  = lane >> 4;
    int ofsA[2], colA[4], ofsB[2];
    #pragma unroll
    for (int mt = 0; mt < 2; mt++)
        ofsA[mt] = (w_m * 32 + mt * 16 + half8 * 8 + laneq) * 128;
    #pragma unroll
    for (int kt = 0; kt < 4; kt++)
        colA[kt] = ((kt * 2 + hi16) ^ laneq) * 16;
    {
        int kb0 = half8 * 8 + laneq;
        #pragma unroll
        for (int p = 0; p < 2; p++)
            ofsB[p] = kb0 * 128 + ((w_n * 4 + p * 2 + hi16) ^ laneq) * 16;
    }
    // phase-B staging STS offsets [mt][nt] (row rA; rB = +2048)
    int stg[2][4];
    #pragma unroll
    for (int mt = 0; mt < 2; mt++)
        #pragma unroll
        for (int nt = 0; nt < 4; nt++) {
            int u = w_n * 8 + nt * 2 + (t4 >> 1);
            int r = w_m * 32 + mt * 16 + g;
            stg[mt][nt] = r * 256 + (((u ^ (g << 1)) & 15) << 4) + (t4 & 1) * 8;
        }
    // phase-B output pass constants
    const int po_u  = tid & 15;                 // unit within row
    const int po_r0 = tid >> 4;                 // base row (p adds 16)
    const int po_sw = (((po_u ^ ((po_r0 & 7) << 1)) & 15) << 4);

    for (int i = tid; i < HDIM; i += NT) SUB[i] = up_b[i];
    if (tid < BDIM) { C1[tid] = g_c1[tid]; C2[tid] = g_c2[tid]; }

    float s0 = 0.f, q0 = 0.f, s1 = 0.f, q1 = 0.f;

    // ---- prologue: stage chunk 0 (x regs->smem, weights cp.async) ----
    {
        const char* wg = (const char*)g_w2h + tid * 32;
        cpa16(sb + O_W0 + tid * 32, wg);
        cpa16(sb + O_W0 + tid * 32 + 16, wg + 16);
        CPA_COMMIT();

        const float* xr0 = x + (rbase + rq) * HDIM;
        const float* xr1 = xr0 + 64 * HDIM;
        float4 px[8];
        #pragma unroll
        for (int j = 0; j < 4; j++) px[j]     = *(const float4*)(xr0 + q * 4 + j * 16);
        #pragma unroll
        for (int j = 0; j < 4; j++) px[4 + j] = *(const float4*)(xr1 + q * 4 + j * 16);
        #pragma unroll
        for (int j = 0; j < 4; j++) {
            s0 += (px[j].x + px[j].y) + (px[j].z + px[j].w);
            q0 += px[j].x * px[j].x + px[j].y * px[j].y
                + px[j].z * px[j].z + px[j].w * px[j].w;
            s1 += (px[4+j].x + px[4+j].y) + (px[4+j].z + px[4+j].w);
            q1 += px[4+j].x * px[4+j].x + px[4+j].y * px[4+j].y
                + px[4+j].z * px[4+j].z + px[4+j].w * px[4+j].w;
        }
        #pragma unroll
        for (int j = 0; j < 4; j++) {
            *(uint2*)(smc + O_XA0 + stsA[j]) =
                make_uint2(pk2(px[j].x, px[j].y), pk2(px[j].z, px[j].w));
            *(uint2*)(smc + O_XA0 + stsA[j] + 8192) =
                make_uint2(pk2(px[4+j].x, px[4+j].y), pk2(px[4+j].z, px[4+j].w));
        }
        CPA_WAIT0();
    }
    __syncthreads();

    // ---- phase A: down GEMM, K=1024 in 16 chunks of 64 ----
    float acc[2][4][4];
    #pragma unroll
    for (int mt = 0; mt < 2; mt++)
        #pragma unroll
        for (int nt = 0; nt < 4; nt++)
            #pragma unroll
            for (int j = 0; j < 4; j++) acc[mt][nt][j] = 0.f;

    for (int c = 0; c < 16; c++) {
        float4 px[8];
        if (c + 1 < 16) {
            const int wN = (c & 1) ? O_W0 : O_W1;
            const char* wg = (const char*)g_w2h + (c + 1) * 8192 + tid * 32;
            cpa16(sb + wN + tid * 32, wg);
            cpa16(sb + wN + tid * 32 + 16, wg + 16);
            CPA_COMMIT();
            const float* xr0 = x + (rbase + rq) * HDIM + (c + 1) * 64;
            const float* xr1 = xr0 + 64 * HDIM;
            #pragma unroll
            for (int j = 0; j < 4; j++) px[j]     = *(const float4*)(xr0 + q * 4 + j * 16);
            #pragma unroll
            for (int j = 0; j < 4; j++) px[4 + j] = *(const float4*)(xr1 + q * 4 + j * 16);
        }
        const uint32_t xaB = sb + ((c & 1) ? O_XA1 : O_XA0);
        const uint32_t wB  = sb + ((c & 1) ? O_W1  : O_W0);
        #pragma unroll
        for (int kt = 0; kt < 4; kt++) {
            uint32_t a[2][4], b[2][4];
            ldm4 (a[0], xaB + ofsA[0] + colA[kt]);
            ldm4 (a[1], xaB + ofsA[1] + colA[kt]);
            ldm4t(b[0], wB + kt * 2048 + ofsB[0]);
            ldm4t(b[1], wB + kt * 2048 + ofsB[1]);
            #pragma unroll
            for (int mt = 0; mt < 2; mt++) {
                mma16(acc[mt][0], a[mt], b[0][0], b[0][1]);
                mma16(acc[mt][1], a[mt], b[0][2], b[0][3]);
                mma16(acc[mt][2], a[mt], b[1][0], b[1][1]);
                mma16(acc[mt][3], a[mt], b[1][2], b[1][3]);
            }
        }
        if (c + 1 < 16) {
            const int xaN = (c & 1) ? O_XA0 : O_XA1;
            #pragma unroll
            for (int j = 0; j < 4; j++) {
                s0 += (px[j].x + px[j].y) + (px[j].z + px[j].w);
                q0 += px[j].x * px[j].x + px[j].y * px[j].y
                    + px[j].z * px[j].z + px[j].w * px[j].w;
                s1 += (px[4+j].x + px[4+j].y) + (px[4+j].z + px[4+j].w);
                q1 += px[4+j].x * px[4+j].x + px[4+j].y * px[4+j].y
                    + px[4+j].z * px[4+j].z + px[4+j].w * px[4+j].w;
            }
            #pragma unroll
            for (int j = 0; j < 4; j++) {
                *(uint2*)(smc + xaN + stsA[j]) =
                    make_uint2(pk2(px[j].x, px[j].y), pk2(px[j].z, px[j].w));
                *(uint2*)(smc + xaN + stsA[j] + 8192) =
                    make_uint2(pk2(px[4+j].x, px[4+j].y), pk2(px[4+j].z, px[4+j].w));
            }
            CPA_WAIT0();
        }
        __syncthreads();
    }

    // ---- LN stats: reduce over the 4 q-lanes ----
    {
        s0 += __shfl_xor_sync(0xffffffffu, s0, 1);
        s0 += __shfl_xor_sync(0xffffffffu, s0, 2);
        q0 += __shfl_xor_sync(0xffffffffu, q0, 1);
        q0 += __shfl_xor_sync(0xffffffffu, q0, 2);
        s1 += __shfl_xor_sync(0xffffffffu, s1, 1);
        s1 += __shfl_xor_sync(0xffffffffu, s1, 2);
        q1 += __shfl_xor_sync(0xffffffffu, q1, 1);
        q1 += __shfl_xor_sync(0xffffffffu, q1, 2);
        if (q == 0) {
            float mu  = s0 * (1.0f / HDIM);
            float var = fmaxf(q0 * (1.0f / HDIM) - mu * mu, 0.0f);
            MU[rq] = mu;
            RS[rq] = rsqrtf(var + 1e-5f);
            mu  = s1 * (1.0f / HDIM);
            var = fmaxf(q1 * (1.0f / HDIM) - mu * mu, 0.0f);
            MU[rq + 64] = mu;
            RS[rq + 64] = rsqrtf(var + 1e-5f);
        }
    }
    __syncthreads();

    // ---- epilogue A: LN fixup + bias + exact GELU -> fp16 h image ----
    #pragma unroll
    for (int mt = 0; mt < 2; mt++) {
        int rA = w_m * 32 + mt * 16 + g, rB = rA + 8;
        float mu1 = MU[rA], rs1 = RS[rA], mu2 = MU[rB], rs2 = RS[rB];
        #pragma unroll
        for (int nt = 0; nt < 4; nt++) {
            int n = w_n * 32 + nt * 8 + 2 * t4;
            float c1a = C1[n], c1b = C1[n + 1];
            float c2a = C2[n], c2b = C2[n + 1];
            float g0 = gelu(rs1 * (acc[mt][nt][0] - mu1 * c1a) + c2a);
            float g1 = gelu(rs1 * (acc[mt][nt][1] - mu1 * c1b) + c2b);
            float g2 = gelu(rs2 * (acc[mt][nt][2] - mu2 * c1a) + c2a);
            float g3 = gelu(rs2 * (acc[mt][nt][3] - mu2 * c1b) + c2b);
            int u = (w_n * 4 + nt);
            *(uint32_t*)(smc + O_H + rA * 128 + ((u ^ g) * 16) + t4 * 4) = pk2(g0, g1);
            *(uint32_t*)(smc + O_H + rB * 128 + ((u ^ g) * 16) + t4 * 4) = pk2(g2, g3);
        }
    }
    // stage up-w chunk 15 (phase B runs n-chunks in REVERSE for L2 locality)
    {
        const char* ug = (const char*)g_uph + 15 * 8192 + tid * 32;
        cpa16(sb + O_W0 + tid * 32, ug);
        cpa16(sb + O_W0 + tid * 32 + 16, ug + 16);
        CPA_COMMIT();
        CPA_WAIT0();
    }
    __syncthreads();

    // ---- phase B prologue: h fragments from smem image ----
    uint32_t ha[4][2][4];
    #pragma unroll
    for (int kt = 0; kt < 4; kt++)
        #pragma unroll
        for (int mt = 0; mt < 2; mt++)
            ldm4(ha[kt][mt], sb + O_H + ofsA[mt] + colA[kt]);
    __syncthreads();   // staging below overwrites the h image — all ha loads must land

    // ---- phase B: up GEMM (K=64), n-chunks 15 -> 0 (reverse, LRU-friendly) ----
    for (int ci = 0; ci < 16; ci++) {
        const int nc = 15 - ci;
        const int buf = ci & 1;                 // ci=0 -> W0 (preloaded)
        if (ci + 1 < 16) {
            const int wN = buf ? O_W0 : O_W1;
            const char* ug = (const char*)g_uph + (nc - 1) * 8192 + tid * 32;
            cpa16(sb + wN + tid * 32, ug);
            cpa16(sb + wN + tid * 32 + 16, ug + 16);
            CPA_COMMIT();
        }
        const uint32_t uwB = sb + (buf ? O_W1 : O_W0);
        float ub[2][4][4];
        #pragma unroll
        for (int mt = 0; mt < 2; mt++)
            #pragma unroll
            for (int nt = 0; nt < 4; nt++)
                #pragma unroll
                for (int j = 0; j < 4; j++) ub[mt][nt][j] = 0.f;

        #pragma unroll
        for (int kt = 0; kt < 4; kt++) {
            uint32_t b[2][4];
            ldm4t(b[0], uwB + kt * 2048 + ofsB[0]);
            ldm4t(b[1], uwB + kt * 2048 + ofsB[1]);
            #pragma unroll
            for (int mt = 0; mt < 2; mt++) {
                mma16(ub[mt][0], ha[kt][mt], b[0][0], b[0][1]);
                mma16(ub[mt][1], ha[kt][mt], b[0][2], b[0][3]);
                mma16(ub[mt][2], ha[kt][mt], b[1][0], b[1][1]);
                mma16(ub[mt][3], ha[kt][mt], b[1][2], b[1][3]);
            }
        }

        // stage fragments -> fp32 tile (swizzled)
        #pragma unroll
        for (int mt = 0; mt < 2; mt++)
            #pragma unroll
            for (int nt = 0; nt < 4; nt++) {
                *(float2*)(smc + O_S + stg[mt][nt]) =
                    make_float2(ub[mt][nt][0], ub[mt][nt][1]);
                *(float2*)(smc + O_S + stg[mt][nt] + 2048) =
                    make_float2(ub[mt][nt][2], ub[mt][nt][3]);
            }
        __syncthreads();

        // coalesced output pass: residual + bias + store (plain LDG/STG)
        {
            float4 bb = *(const float4*)(SUB + nc * 64 + po_u * 4);
            #pragma unroll
            for (int p = 0; p < 8; p++) {
                int r = po_r0 + p * 16;
                float4 v  = *(const float4*)(smc + O_S + r * 256 + po_sw);
                const size_t go = (rbase + r) * HDIM + nc * 64 + po_u * 4;
                float4 xv = *(const float4*)(x + go);
                float4 o;
                o.x = xv.x + v.x + bb.x;
                o.y = xv.y + v.y + bb.y;
                o.z = xv.z + v.z + bb.z;
                o.w = xv.w + v.w + bb.w;
                *(float4*)(out + go) = o;
            }
        }
        if (ci + 1 < 16) CPA_WAIT0();
        __syncthreads();
    }
}

// ---------------- launch ----------------
extern "C" void kernel_launch(void* const* d_in, const int* in_sizes, int n_in,
                              void* d_out, int out_size) {
    const float* x      = (const float*)d_in[0];
    const float* norm_w = (const float*)d_in[1];
    const float* norm_b = (const float*)d_in[2];
    const float* down_w = (const float*)d_in[3];
    const float* down_b = (const float*)d_in[4];
    const float* up_w   = (const float*)d_in[5];
    const float* up_b   = (const float*)d_in[6];
    float* out = (float*)d_out;

    int rows = in_sizes[0] / HDIM;

    cudaFuncSetAttribute(adapter_main,
                         cudaFuncAttributeMaxDynamicSharedMemorySize, SMEM_BYTES);

    prep_all<<<BDIM, 256>>>(down_w, norm_w, norm_b, down_b, up_w);
    adapter_main<<<rows / TM, NT, SMEM_BYTES>>>(x, up_b, out);
}